// round 7
// baseline (speedup 1.0000x reference)
#include <cuda_runtime.h>

#define D      64
#define NSEG   8192
#define OUT    128

// Scratch: per-segment relu'd linear outputs. 2*8192*128*4 = 8 MB.
__device__ float g_h[2 * NSEG * OUT];

__device__ __forceinline__ void fmax4(float4& a, const float4 b) {
    a.x = fmaxf(a.x, b.x); a.y = fmaxf(a.y, b.y);
    a.z = fmaxf(a.z, b.z); a.w = fmaxf(a.w, b.w);
}

// ---------------------------------------------------------------------------
// Kernel 1 (fused): per-segment max over contiguous row range (streaming loop
// unchanged — measured at the DRAM wall, 6.6 TB/s), then the per-segment
// 64->128 linear + bias + relu computed in the block epilogue (hidden under
// other blocks' streaming; W stays L1-resident, 64 KB for both types), result
// written to g_h[seg][128] coalesced.
// ptr arrays are int32 (JAX x64 disabled downcasts the int64 ptr).
// ---------------------------------------------------------------------------
__global__ void __launch_bounds__(256)
seg_max_linear_kernel(const float* __restrict__ x_a,
                      const float* __restrict__ x_b,
                      const float* __restrict__ W_a,
                      const float* __restrict__ W_b,
                      const float* __restrict__ b_a,
                      const float* __restrict__ b_b,
                      const int* __restrict__ ptr_a,
                      const int* __restrict__ ptr_b,
                      float* __restrict__ out)
{
    const int bid  = blockIdx.x;               // [0, 2*NSEG)
    const int type = (bid >= NSEG) ? 1 : 0;
    const int g    = type ? (bid - NSEG) : bid;

    const float* x   = type ? x_b   : x_a;
    const int*   ptr = type ? ptr_b : ptr_a;

    const int s = ptr[g];
    const int e = ptr[g + 1];

    const int tid = threadIdx.x;               // 256
    const int c4  = tid & 15;                  // float4 column 0..15
    const int rg  = tid >> 4;                  // row group 0..15

    const float NEG = -3.402823466e38f;
    float4 m0 = make_float4(NEG, NEG, NEG, NEG);
    float4 m1 = m0, m2 = m0, m3 = m0;

    const float4* __restrict__ xv = reinterpret_cast<const float4*>(x);

    long long row = (long long)s + rg;
    for (; row + 48 < e; row += 64) {
        const float4* p = xv + row * (D / 4) + c4;
        float4 v0 = __ldcs(p);
        float4 v1 = __ldcs(p + 16 * (D / 4));
        float4 v2 = __ldcs(p + 32 * (D / 4));
        float4 v3 = __ldcs(p + 48 * (D / 4));
        fmax4(m0, v0); fmax4(m1, v1); fmax4(m2, v2); fmax4(m3, v3);
    }
    for (; row < e; row += 16) {
        float4 v0 = __ldcs(xv + row * (D / 4) + c4);
        fmax4(m0, v0);
    }
    fmax4(m0, m1); fmax4(m2, m3); fmax4(m0, m2);

    __shared__ float4 sm[16][16];
    __shared__ float4 sfin[D / 4];             // final segment max (64 floats)

    sm[rg][c4] = m0;
    __syncthreads();

    if (tid < 16) {
        float4 m = sm[0][tid];
        #pragma unroll
        for (int j = 1; j < 16; j++)
            fmax4(m, sm[j][tid]);
        sfin[tid] = m;
    }
    __syncthreads();

    // Epilogue: per-segment linear + bias + relu -> g_h[seg][o], coalesced.
    if (tid < OUT) {
        const int o = tid;
        const float* __restrict__ W    = type ? W_b : W_a;
        const float* __restrict__ bias = type ? b_b : b_a;
        const float4* __restrict__ W4  =
            reinterpret_cast<const float4*>(W + o * D);

        float a0 = 0.f, a1 = 0.f, a2 = 0.f, a3 = 0.f;
        #pragma unroll
        for (int k = 0; k < D / 4; k++) {
            float4 w = W4[k];
            float4 u = sfin[k];
            a0 = fmaf(w.x, u.x, a0);
            a1 = fmaf(w.y, u.y, a1);
            a2 = fmaf(w.z, u.z, a2);
            a3 = fmaf(w.w, u.w, a3);
        }
        float h = bias[o] + ((a0 + a1) + (a2 + a3));
        g_h[(size_t)(type * NSEG + g) * OUT + o] = fmaxf(h, 0.0f);
    }

    // Initialize output to 0 (== relu floor); ordered before kernel 2 by
    // stream order (kernel 2's atomics run only after this kernel completes).
    if (bid == 0 && tid < OUT) out[tid] = 0.0f;
}

// ---------------------------------------------------------------------------
// Kernel 2: streaming max-reduce of g_h (16384 x 128, all values >= 0).
// 256 blocks x 256 threads; each block reduces 64 rows (thread layout:
// 32 float4-cols x 8 row-groups), then 32 threads publish via atomicMax
// (32K total atomics, 256 per address -- negligible).
// int-bit atomicMax is exact ordering for non-negative IEEE floats.
// ---------------------------------------------------------------------------
__global__ void __launch_bounds__(256)
reduce_max_kernel(float* __restrict__ out)
{
    const int tid = threadIdx.x;
    const int c4  = tid & 31;                  // float4 column 0..31
    const int rg  = tid >> 5;                  // row group 0..7
    const int r0  = blockIdx.x * 64;           // 256 blocks * 64 rows = 16384

    const float4* __restrict__ h4 = reinterpret_cast<const float4*>(g_h);

    float4 m = make_float4(0.f, 0.f, 0.f, 0.f);   // h >= 0 after relu
    #pragma unroll
    for (int r = rg; r < 64; r += 8)
        fmax4(m, __ldcs(h4 + (size_t)(r0 + r) * (OUT / 4) + c4));

    __shared__ float4 sm2[8][32];
    sm2[rg][c4] = m;
    __syncthreads();

    if (tid < 32) {
        float4 v = sm2[0][tid];
        #pragma unroll
        for (int j = 1; j < 8; j++)
            fmax4(v, sm2[j][tid]);
        int* o = reinterpret_cast<int*>(out) + tid * 4;
        atomicMax(o + 0, __float_as_int(v.x));
        atomicMax(o + 1, __float_as_int(v.y));
        atomicMax(o + 2, __float_as_int(v.z));
        atomicMax(o + 3, __float_as_int(v.w));
    }
}

// ---------------------------------------------------------------------------
extern "C" void kernel_launch(void* const* d_in, const int* in_sizes, int n_in,
                              void* d_out, int out_size)
{
    const float* x_a   = (const float*)d_in[0];
    const float* x_b   = (const float*)d_in[1];
    const float* W_a   = (const float*)d_in[2];
    const float* W_b   = (const float*)d_in[3];
    const float* b_a   = (const float*)d_in[4];
    const float* b_b   = (const float*)d_in[5];
    const int*   ptr_a = (const int*)d_in[6];
    const int*   ptr_b = (const int*)d_in[7];
    float* out = (float*)d_out;

    seg_max_linear_kernel<<<2 * NSEG, 256>>>(x_a, x_b, W_a, W_b, b_a, b_b,
                                             ptr_a, ptr_b, out);
    reduce_max_kernel<<<256, 256>>>(out);
}

// round 9
// speedup vs baseline: 1.0492x; 1.0492x over previous
#include <cuda_runtime.h>

#define D      64
#define NSEG   8192
#define OUT    128

__device__ __forceinline__ void fmax4(float4& a, const float4 b) {
    a.x = fmaxf(a.x, b.x); a.y = fmaxf(a.y, b.y);
    a.z = fmaxf(a.z, b.z); a.w = fmaxf(a.w, b.w);
}

// ---------------------------------------------------------------------------
// Init: zero the output (== relu floor). Runs before the fused kernel each
// replay (stream order), so atomicMax accumulation is reset deterministically.
// ---------------------------------------------------------------------------
__global__ void init_out_kernel(float* __restrict__ out)
{
    out[threadIdx.x] = 0.0f;
}

// ---------------------------------------------------------------------------
// Fused kernel: per-segment max over contiguous row range (streaming loop
// byte-identical to the R3 kernel measured at the DRAM wall, 6.6 TB/s),
// then per-segment 64->128 linear + bias + relu in the epilogue, published
// directly via per-channel atomicMax (128 distinct addresses; int-bit
// atomicMax is exact ordering for non-negative IEEE floats).
//
// Register discipline (the R7 lesson): __launch_bounds__(256, 4) caps regs at
// 64 so >=4 blocks stay resident per SM for the stream, and the W loop is
// only unrolled 4x so at most 4 W float4s are live at once.
// ptr arrays are int32 (JAX x64 disabled downcasts the int64 ptr).
// ---------------------------------------------------------------------------
__global__ void __launch_bounds__(256, 4)
seg_max_linear_kernel(const float* __restrict__ x_a,
                      const float* __restrict__ x_b,
                      const float* __restrict__ W_a,
                      const float* __restrict__ W_b,
                      const float* __restrict__ b_a,
                      const float* __restrict__ b_b,
                      const int* __restrict__ ptr_a,
                      const int* __restrict__ ptr_b,
                      float* __restrict__ out)
{
    const int bid  = blockIdx.x;               // [0, 2*NSEG)
    const int type = (bid >= NSEG) ? 1 : 0;
    const int g    = type ? (bid - NSEG) : bid;

    const float* x   = type ? x_b   : x_a;
    const int*   ptr = type ? ptr_b : ptr_a;

    const int s = ptr[g];
    const int e = ptr[g + 1];

    const int tid = threadIdx.x;               // 256
    const int c4  = tid & 15;                  // float4 column 0..15
    const int rg  = tid >> 4;                  // row group 0..15

    const float NEG = -3.402823466e38f;
    float4 m0 = make_float4(NEG, NEG, NEG, NEG);
    float4 m1 = m0, m2 = m0, m3 = m0;

    const float4* __restrict__ xv = reinterpret_cast<const float4*>(x);

    long long row = (long long)s + rg;
    for (; row + 48 < e; row += 64) {
        const float4* p = xv + row * (D / 4) + c4;
        float4 v0 = __ldcs(p);
        float4 v1 = __ldcs(p + 16 * (D / 4));
        float4 v2 = __ldcs(p + 32 * (D / 4));
        float4 v3 = __ldcs(p + 48 * (D / 4));
        fmax4(m0, v0); fmax4(m1, v1); fmax4(m2, v2); fmax4(m3, v3);
    }
    for (; row < e; row += 16) {
        float4 v0 = __ldcs(xv + row * (D / 4) + c4);
        fmax4(m0, v0);
    }
    fmax4(m0, m1); fmax4(m2, m3); fmax4(m0, m2);

    __shared__ float4 sm[16][16];
    __shared__ float4 sfin[D / 4];             // final segment max (64 floats)

    sm[rg][c4] = m0;
    __syncthreads();

    if (tid < 16) {
        float4 m = sm[0][tid];
        #pragma unroll
        for (int j = 1; j < 16; j++)
            fmax4(m, sm[j][tid]);
        sfin[tid] = m;
    }
    __syncthreads();

    // Epilogue: one output channel per thread (threads 0..127).
    if (tid < OUT) {
        const int o = tid;
        const float* __restrict__ W    = type ? W_b : W_a;
        const float* __restrict__ bias = type ? b_b : b_a;
        const float4* __restrict__ W4  =
            reinterpret_cast<const float4*>(W + o * D);

        float a0 = 0.f, a1 = 0.f, a2 = 0.f, a3 = 0.f;
        #pragma unroll 4
        for (int k = 0; k < D / 4; k++) {
            float4 w = W4[k];
            float4 u = sfin[k];
            a0 = fmaf(w.x, u.x, a0);
            a1 = fmaf(w.y, u.y, a1);
            a2 = fmaf(w.z, u.z, a2);
            a3 = fmaf(w.w, u.w, a3);
        }
        float h = bias[o] + ((a0 + a1) + (a2 + a3));
        float lmax = fmaxf(h, 0.0f);           // relu floor, value >= 0
        atomicMax(reinterpret_cast<int*>(out) + o, __float_as_int(lmax));
    }
}

// ---------------------------------------------------------------------------
extern "C" void kernel_launch(void* const* d_in, const int* in_sizes, int n_in,
                              void* d_out, int out_size)
{
    const float* x_a   = (const float*)d_in[0];
    const float* x_b   = (const float*)d_in[1];
    const float* W_a   = (const float*)d_in[2];
    const float* W_b   = (const float*)d_in[3];
    const float* b_a   = (const float*)d_in[4];
    const float* b_b   = (const float*)d_in[5];
    const int*   ptr_a = (const int*)d_in[6];
    const int*   ptr_b = (const int*)d_in[7];
    float* out = (float*)d_out;

    init_out_kernel<<<1, OUT>>>(out);
    seg_max_linear_kernel<<<2 * NSEG, 256>>>(x_a, x_b, W_a, W_b, b_a, b_b,
                                             ptr_a, ptr_b, out);
}

// round 10
// speedup vs baseline: 1.2118x; 1.1549x over previous
#include <cuda_runtime.h>

#define D      64
#define NSEG   8192
#define OUT    128
#define S      8     // segments per block

__device__ __forceinline__ void fmax4(float4& a, const float4 b) {
    a.x = fmaxf(a.x, b.x); a.y = fmaxf(a.y, b.y);
    a.z = fmaxf(a.z, b.z); a.w = fmaxf(a.w, b.w);
}

// ---------------------------------------------------------------------------
// Init: zero the output (== relu floor). Stream-ordered before the fused
// kernel, so atomicMax accumulation is reset deterministically per replay.
// ---------------------------------------------------------------------------
__global__ void init_out_kernel(float* __restrict__ out)
{
    out[threadIdx.x] = 0.0f;
}

// ---------------------------------------------------------------------------
// Fused kernel, W-amortized: each block handles S=8 consecutive segments of
// one type. Streaming inner loop is byte-identical to the R3 kernel (measured
// at the DRAM wall). W (32 KB) is copied global->shared ONCE per block,
// coalesced, into a padded conflict-free layout (row stride 9 float4s ->
// bank = 4*t mod 32, distinct within each 8-lane phase); the R9 lesson was
// that per-segment strided W LDGs cost 32 L1-wavefronts each and strangled
// the stream (L1=72%, DRAM 63.8%).
// Phase B: split-K pairs in-warp (o=tid>>1, h=tid&1), halves combined with
// shfl_xor(1); per-channel atomicMax publishes (int-bit atomicMax is exact
// ordering for non-negative IEEE floats; relu(max)==max(relu)).
// ptr arrays are int32 (JAX x64 disabled downcasts the int64 ptr).
// ---------------------------------------------------------------------------
__global__ void __launch_bounds__(256, 4)
seg_max_linear_kernel(const float* __restrict__ x_a,
                      const float* __restrict__ x_b,
                      const float* __restrict__ W_a,
                      const float* __restrict__ W_b,
                      const float* __restrict__ b_a,
                      const float* __restrict__ b_b,
                      const int* __restrict__ ptr_a,
                      const int* __restrict__ ptr_b,
                      float* __restrict__ out)
{
    const int blocks_per_type = NSEG / S;             // 1024
    const int bid   = blockIdx.x;                     // [0, 2048)
    const int type  = (bid >= blocks_per_type) ? 1 : 0;
    const int gbase = (type ? (bid - blocks_per_type) : bid) * S;

    const float* x    = type ? x_b   : x_a;
    const int*   ptr  = type ? ptr_b : ptr_a;
    const float* W    = type ? W_b   : W_a;
    const float* bias = type ? b_b   : b_a;

    const int tid = threadIdx.x;               // 256
    const int c4  = tid & 15;                  // float4 column 0..15
    const int rg  = tid >> 4;                  // row group 0..15

    __shared__ float4 sw[256][9];              // padded W: 36 KB, conflict-free
    __shared__ float4 sm[16][16];              // per-segment reduce scratch
    __shared__ float4 seg[S][D / 4];           // S segment-max vectors

    // W -> shared, coalesced LDG, conflict-free scattered STS.
    // Thread t'=(row<<1)|(kk>>3) owns slot kk&7 of its (o,h) half-row.
    {
        const float4* __restrict__ W4g = reinterpret_cast<const float4*>(W);
        #pragma unroll
        for (int i = 0; i < 8; i++) {
            int f = tid + i * 256;             // float4 linear index into W
            float4 v = W4g[f];
            int row = f >> 4;                  // output row 0..127
            int kk  = f & 15;                  // float4 within row
            sw[(row << 1) | (kk >> 3)][kk & 7] = v;
        }
    }
    // (visibility of sw to other threads is covered by the per-segment
    //  __syncthreads below, all of which precede phase B)

    const float4* __restrict__ xv = reinterpret_cast<const float4*>(x);
    const float NEG = -3.402823466e38f;

    for (int s = 0; s < S; s++) {
        const int gs = ptr[gbase + s];
        const int ge = ptr[gbase + s + 1];

        float4 m0 = make_float4(NEG, NEG, NEG, NEG);
        float4 m1 = m0, m2 = m0, m3 = m0;

        long long row = (long long)gs + rg;
        for (; row + 48 < ge; row += 64) {
            const float4* p = xv + row * (D / 4) + c4;
            float4 v0 = __ldcs(p);
            float4 v1 = __ldcs(p + 16 * (D / 4));
            float4 v2 = __ldcs(p + 32 * (D / 4));
            float4 v3 = __ldcs(p + 48 * (D / 4));
            fmax4(m0, v0); fmax4(m1, v1); fmax4(m2, v2); fmax4(m3, v3);
        }
        for (; row < ge; row += 16) {
            float4 v0 = __ldcs(xv + row * (D / 4) + c4);
            fmax4(m0, v0);
        }
        fmax4(m0, m1); fmax4(m2, m3); fmax4(m0, m2);

        sm[rg][c4] = m0;
        __syncthreads();

        if (tid < 16) {
            float4 m = sm[0][tid];
            #pragma unroll
            for (int j = 1; j < 16; j++)
                fmax4(m, sm[j][tid]);
            seg[s][tid] = m;
        }
        __syncthreads();                       // sm reusable next segment
    }

    // Phase B: split-K linear + bias + relu + running max over S segments.
    {
        const int o = tid >> 1;                // output channel 0..127
        const int h = tid & 1;                 // K-half (paired lanes)

        float4 w[8];                           // W[o, h*32 .. h*32+32)
        #pragma unroll
        for (int k = 0; k < 8; k++) w[k] = sw[tid][k];
        const float bo = bias[o];

        float lmax = 0.0f;                     // relu floor
        #pragma unroll
        for (int s = 0; s < S; s++) {
            float a0 = 0.f, a1 = 0.f, a2 = 0.f, a3 = 0.f;
            #pragma unroll
            for (int k = 0; k < 8; k++) {
                float4 u  = seg[s][h * 8 + k];
                float4 ww = w[k];
                a0 = fmaf(ww.x, u.x, a0);
                a1 = fmaf(ww.y, u.y, a1);
                a2 = fmaf(ww.z, u.z, a2);
                a3 = fmaf(ww.w, u.w, a3);
            }
            float hd    = (a0 + a1) + (a2 + a3);
            float other = __shfl_xor_sync(0xffffffffu, hd, 1);
            lmax = fmaxf(lmax, hd + other + bo);
        }

        if (h == 0)
            atomicMax(reinterpret_cast<int*>(out) + o, __float_as_int(lmax));
    }
}

// ---------------------------------------------------------------------------
extern "C" void kernel_launch(void* const* d_in, const int* in_sizes, int n_in,
                              void* d_out, int out_size)
{
    const float* x_a   = (const float*)d_in[0];
    const float* x_b   = (const float*)d_in[1];
    const float* W_a   = (const float*)d_in[2];
    const float* W_b   = (const float*)d_in[3];
    const float* b_a   = (const float*)d_in[4];
    const float* b_b   = (const float*)d_in[5];
    const int*   ptr_a = (const int*)d_in[6];
    const int*   ptr_b = (const int*)d_in[7];
    float* out = (float*)d_out;

    init_out_kernel<<<1, OUT>>>(out);
    seg_max_linear_kernel<<<2 * (NSEG / S), 256>>>(x_a, x_b, W_a, W_b,
                                                   b_a, b_b, ptr_a, ptr_b, out);
}

// round 11
// speedup vs baseline: 1.3019x; 1.0743x over previous
#include <cuda_runtime.h>

#define D      64
#define NSEG   8192
#define OUT    128
#define NBLK   592   // 148 SMs x 4 resident blocks (64-reg cap)

__device__ int g_counter[2];   // dynamic segment queues, one per type

__device__ __forceinline__ void fmax4(float4& a, const float4 b) {
    a.x = fmaxf(a.x, b.x); a.y = fmaxf(a.y, b.y);
    a.z = fmaxf(a.z, b.z); a.w = fmaxf(a.w, b.w);
}

// ---------------------------------------------------------------------------
// Init: zero output (== relu floor) and both work-queue counters.
// Stream-ordered before the main kernel -> deterministic per replay.
// ---------------------------------------------------------------------------
__global__ void init_kernel(float* __restrict__ out)
{
    out[threadIdx.x] = 0.0f;
    if (threadIdx.x < 2) g_counter[threadIdx.x] = 0;
}

// ---------------------------------------------------------------------------
// Persistent fused kernel. 592 blocks; block parity picks the type (a/b) so
// each block loads its 32 KB W into shared exactly once. Segments are pulled
// from a global atomicAdd queue -> no wave quantization, self-balancing
// (the R10 lesson: static 8-seg blocks at 3.5 waves left 15% on the table).
//
// Per segment: R3 streaming max loop (measured at the DRAM wall) -> 2-level
// shared reduce -> split-K epilogue straight from the conflict-free padded
// smem W (sw[256][9] float4: word index 36t+4k -> bank 4t mod 32, distinct
// within each 8-lane LDS.128 phase). lmax accumulates in registers across all
// segments; one atomicMax per (o) pair at block exit.
// relu(max)==max(relu); int-bit atomicMax exact for non-negative floats.
// ptr arrays are int32 (JAX x64 disabled downcasts the int64 ptr).
// ---------------------------------------------------------------------------
__global__ void __launch_bounds__(256, 4)
seg_max_linear_kernel(const float* __restrict__ x_a,
                      const float* __restrict__ x_b,
                      const float* __restrict__ W_a,
                      const float* __restrict__ W_b,
                      const float* __restrict__ b_a,
                      const float* __restrict__ b_b,
                      const int* __restrict__ ptr_a,
                      const int* __restrict__ ptr_b,
                      float* __restrict__ out)
{
    const int ctype = blockIdx.x & 1;

    const float* x    = ctype ? x_b   : x_a;
    const int*   ptr  = ctype ? ptr_b : ptr_a;
    const float* W    = ctype ? W_b   : W_a;
    const float* bias = ctype ? b_b   : b_a;

    const int tid = threadIdx.x;               // 256
    const int c4  = tid & 15;                  // float4 column 0..15
    const int rg  = tid >> 4;                  // row group 0..15
    const int o   = tid >> 1;                  // epilogue output channel
    const int h   = tid & 1;                   // epilogue K-half

    __shared__ float4 sw[256][9];              // padded W, conflict-free
    __shared__ float4 sm[16][16];              // reduce scratch
    __shared__ float4 segv[D / 4];             // this segment's max vector
    __shared__ int    swork;

    // W -> shared once: coalesced LDG, scattered conflict-free STS.
    {
        const float4* __restrict__ W4g = reinterpret_cast<const float4*>(W);
        #pragma unroll
        for (int i = 0; i < 8; i++) {
            int f = tid + i * 256;             // float4 linear index into W
            float4 v = W4g[f];
            int row = f >> 4;                  // output row 0..127
            int kk  = f & 15;                  // float4 within row
            sw[(row << 1) | (kk >> 3)][kk & 7] = v;
        }
    }
    const float bo = bias[o];                  // L1-resident, 2 lanes/addr

    const float4* __restrict__ xv = reinterpret_cast<const float4*>(x);
    const float NEG = -3.402823466e38f;

    float lmax = 0.0f;                         // relu floor, running block max

    while (true) {
        if (tid == 0) swork = atomicAdd(&g_counter[ctype], 1);
        __syncthreads();                       // also covers sw visibility
        const int g = swork;
        if (g >= NSEG) break;

        const int gs = ptr[g];
        const int ge = ptr[g + 1];

        float4 m0 = make_float4(NEG, NEG, NEG, NEG);
        float4 m1 = m0, m2 = m0, m3 = m0;

        long long row = (long long)gs + rg;
        for (; row + 48 < ge; row += 64) {
            const float4* p = xv + row * (D / 4) + c4;
            float4 v0 = __ldcs(p);
            float4 v1 = __ldcs(p + 16 * (D / 4));
            float4 v2 = __ldcs(p + 32 * (D / 4));
            float4 v3 = __ldcs(p + 48 * (D / 4));
            fmax4(m0, v0); fmax4(m1, v1); fmax4(m2, v2); fmax4(m3, v3);
        }
        for (; row < ge; row += 16) {
            float4 v0 = __ldcs(xv + row * (D / 4) + c4);
            fmax4(m0, v0);
        }
        fmax4(m0, m1); fmax4(m2, m3); fmax4(m0, m2);

        sm[rg][c4] = m0;
        __syncthreads();

        if (tid < 16) {
            float4 m = sm[0][tid];
            #pragma unroll
            for (int j = 1; j < 16; j++)
                fmax4(m, sm[j][tid]);
            segv[tid] = m;
        }
        __syncthreads();

        // Epilogue: split-K half-dot from smem W (no register W copy).
        float a0 = 0.f, a1 = 0.f, a2 = 0.f, a3 = 0.f;
        #pragma unroll
        for (int k = 0; k < 8; k++) {
            float4 ww = sw[tid][k];            // W[o, h*32+4k .. +4)
            float4 u  = segv[h * 8 + k];
            a0 = fmaf(ww.x, u.x, a0);
            a1 = fmaf(ww.y, u.y, a1);
            a2 = fmaf(ww.z, u.z, a2);
            a3 = fmaf(ww.w, u.w, a3);
        }
        float hd    = (a0 + a1) + (a2 + a3);
        float other = __shfl_xor_sync(0xffffffffu, hd, 1);
        lmax = fmaxf(lmax, hd + other + bo);
        // next iteration's top-of-loop __syncthreads orders segv reuse
    }

    if (h == 0)
        atomicMax(reinterpret_cast<int*>(out) + o, __float_as_int(lmax));
}

// ---------------------------------------------------------------------------
extern "C" void kernel_launch(void* const* d_in, const int* in_sizes, int n_in,
                              void* d_out, int out_size)
{
    const float* x_a   = (const float*)d_in[0];
    const float* x_b   = (const float*)d_in[1];
    const float* W_a   = (const float*)d_in[2];
    const float* W_b   = (const float*)d_in[3];
    const float* b_a   = (const float*)d_in[4];
    const float* b_b   = (const float*)d_in[5];
    const int*   ptr_a = (const int*)d_in[6];
    const int*   ptr_b = (const int*)d_in[7];
    float* out = (float*)d_out;

    init_kernel<<<1, OUT>>>(out);
    seg_max_linear_kernel<<<NBLK, 256>>>(x_a, x_b, W_a, W_b,
                                         b_a, b_b, ptr_a, ptr_b, out);
}